// round 8
// baseline (speedup 1.0000x reference)
#include <cuda_runtime.h>
#include <cstdint>

// ResBlock_71021579207010 — fused binarized ResBlock (B=32, T=8192, C=F=128, K=2, dil=16).
//
// Algebra (verified R4/R5, rel_err ~2e-7):
//   shortcut[b,t,f] = sum_c sign(x[b,t,c]) * sign(w_sc[0,c,f])           (exact binary dot)
//   conv2 input = ste_sign(relu(...)) == +1  =>  conv2 out constant per (t<16 | t>=16)
//   conv1/bn1/w1/beta1/mean1/var1 are dead.
//   out = relu( shortcut + relu(bn2(const)) )
//
// vs R5 (45.7us main, DRAM 59%, alu 41%, issue 40% -> latency-exposed):
//   * explicit register prefetch pipeline (depth 4): ballots never consume a fresh LDG
//   * block-uniform fast path: only 32/2048 blocks contain t<16 rows
//   * streaming cache ops (__ldcs/__stcs) for the touch-once 128MiB x/out streams

#define T_LEN   8192
#define C_DIM   128
#define F_DIM   128
#define B_DIM   32
#define ROWS_TOTAL (B_DIM * T_LEN)      // 262144

__device__ uint4 g_wsc[F_DIM];    // packed sign(w_sc): word k bit l <-> channel c = 4*l + k
__device__ float g_clo[F_DIM];    // 128 + relu(bn2(S1))       for t <  16
__device__ float g_chi[F_DIM];    // 128 + relu(bn2(S0+S1))    for t >= 16

// One warp per output channel f; packing uses the SAME ballot construction the
// main kernel applies to x, so bit conventions match by design.
__global__ void precompute_kernel(const float* __restrict__ w2,    // [2,128,128]
                                  const float* __restrict__ w_sc,  // [1,128,128]
                                  const float* __restrict__ beta2,
                                  const float* __restrict__ mean2,
                                  const float* __restrict__ var2) {
    const int f = blockIdx.x;          // 0..127
    const int l = threadIdx.x;         // lane 0..31

    // word k, bit l  <->  channel c = 4*l + k
    unsigned p0 = __ballot_sync(0xffffffffu, w_sc[(4 * l + 0) * F_DIM + f] < 0.0f);
    unsigned p1 = __ballot_sync(0xffffffffu, w_sc[(4 * l + 1) * F_DIM + f] < 0.0f);
    unsigned p2 = __ballot_sync(0xffffffffu, w_sc[(4 * l + 2) * F_DIM + f] < 0.0f);
    unsigned p3 = __ballot_sync(0xffffffffu, w_sc[(4 * l + 3) * F_DIM + f] < 0.0f);

    // Column sums of sign(w2[k,:,f]): count negatives via ballot popc, 4 chans/lane.
    int n0 = 0, n1 = 0;
    #pragma unroll
    for (int j = 0; j < 4; ++j) {
        int c = 4 * l + j;
        unsigned b0 = __ballot_sync(0xffffffffu, w2[(0 * C_DIM + c) * F_DIM + f] < 0.0f);
        unsigned b1 = __ballot_sync(0xffffffffu, w2[(1 * C_DIM + c) * F_DIM + f] < 0.0f);
        n0 += __popc(b0);
        n1 += __popc(b1);
    }

    if (l == 0) {
        g_wsc[f] = make_uint4(p0, p1, p2, p3);
        float S0 = (float)(C_DIM - 2 * n0);
        float S1 = (float)(C_DIM - 2 * n1);
        float inv = rsqrtf(var2[f] + 1e-3f);
        float lo  = (S1      - mean2[f]) * inv + beta2[f];
        float hi  = (S0 + S1 - mean2[f]) * inv + beta2[f];
        // pre-bias by +C_DIM: out = relu((C_DIM - 2*neq) + relu(bn)) = relu(fma(neq,-2,cst))
        g_clo[f] = fmaxf(lo, 0.0f) + (float)C_DIM;
        g_chi[f] = fmaxf(hi, 0.0f) + (float)C_DIM;
    }
}

#define BLOCK_THREADS 256
#define WARPS_PER_BLOCK (BLOCK_THREADS / 32)              // 8
#define ROWS_PER_WARP 16
#define ROWS_PER_BLOCK (WARPS_PER_BLOCK * ROWS_PER_WARP)  // 128
#define GRID_BLOCKS (ROWS_TOTAL / ROWS_PER_BLOCK)         // 2048
#define PF 4                                              // prefetch depth (rows in flight)
#define STRIDE4 (WARPS_PER_BLOCK * C_DIM / 4)             // 256 float4 between a warp's rows

__device__ __forceinline__ void row_body(const float4 v, const float4 cst,
                                         const uint4 wb0, const uint4 wb1,
                                         const uint4 wb2, const uint4 wb3,
                                         float4* dst) {
    const unsigned a0 = __ballot_sync(0xffffffffu, v.x < 0.0f);
    const unsigned a1 = __ballot_sync(0xffffffffu, v.y < 0.0f);
    const unsigned a2 = __ballot_sync(0xffffffffu, v.z < 0.0f);
    const unsigned a3 = __ballot_sync(0xffffffffu, v.w < 0.0f);

    const int n0 = __popc(a0 ^ wb0.x) + __popc(a1 ^ wb0.y) + __popc(a2 ^ wb0.z) + __popc(a3 ^ wb0.w);
    const int n1 = __popc(a0 ^ wb1.x) + __popc(a1 ^ wb1.y) + __popc(a2 ^ wb1.z) + __popc(a3 ^ wb1.w);
    const int n2 = __popc(a0 ^ wb2.x) + __popc(a1 ^ wb2.y) + __popc(a2 ^ wb2.z) + __popc(a3 ^ wb2.w);
    const int n3 = __popc(a0 ^ wb3.x) + __popc(a1 ^ wb3.y) + __popc(a2 ^ wb3.z) + __popc(a3 ^ wb3.w);

    float4 o;
    o.x = fmaxf(fmaf((float)n0, -2.0f, cst.x), 0.0f);
    o.y = fmaxf(fmaf((float)n1, -2.0f, cst.y), 0.0f);
    o.z = fmaxf(fmaf((float)n2, -2.0f, cst.z), 0.0f);
    o.w = fmaxf(fmaf((float)n3, -2.0f, cst.w), 0.0f);
    __stcs(dst, o);
}

__global__ __launch_bounds__(BLOCK_THREADS)
void resblock_main_kernel(const float* __restrict__ x, float* __restrict__ out) {
    const int lane = threadIdx.x & 31;
    const int warp = threadIdx.x >> 5;
    const int base = blockIdx.x * ROWS_PER_BLOCK;

    // Per-thread weights/constants in registers (f = 4*lane+j is loop-invariant).
    const uint4* wp = (const uint4*)g_wsc + 4 * lane;
    const uint4 wb0 = wp[0];
    const uint4 wb1 = wp[1];
    const uint4 wb2 = wp[2];
    const uint4 wb3 = wp[3];
    const float4 chi = ((const float4*)g_chi)[lane];
    const float4 clo = ((const float4*)g_clo)[lane];

    const size_t row0 = (size_t)(base + warp);
    const float4* __restrict__ src = (const float4*)(x   + row0 * C_DIM) + lane;
    float4*       __restrict__ dst = (float4*)      (out + row0 * F_DIM) + lane;

    // Prefetch pipeline: rows i..i+PF-1 in flight while computing row i.
    float4 buf[PF];
    #pragma unroll
    for (int j = 0; j < PF; ++j) buf[j] = __ldcs(src + j * STRIDE4);

    if ((base & (T_LEN - 1)) != 0) {
        // FAST PATH: every row of this block has t >= 128 > 16 -> constant = chi.
        #pragma unroll
        for (int i = 0; i < ROWS_PER_WARP; ++i) {
            const float4 v = buf[i % PF];
            if (i + PF < ROWS_PER_WARP) buf[i % PF] = __ldcs(src + (i + PF) * STRIDE4);
            row_body(v, chi, wb0, wb1, wb2, wb3, dst + i * STRIDE4);
        }
    } else {
        // SLOW PATH (32 of 2048 blocks): t = warp + i*8; i<2 -> t<16 -> clo, else chi.
        #pragma unroll
        for (int i = 0; i < ROWS_PER_WARP; ++i) {
            const float4 v = buf[i % PF];
            if (i + PF < ROWS_PER_WARP) buf[i % PF] = __ldcs(src + (i + PF) * STRIDE4);
            const float4 cst = (i >= 2) ? chi : clo;      // t = warp + i*8 < 16  <=>  i < 2
            row_body(v, cst, wb0, wb1, wb2, wb3, dst + i * STRIDE4);
        }
    }
}

extern "C" void kernel_launch(void* const* d_in, const int* in_sizes, int n_in,
                              void* d_out, int out_size) {
    // metadata order: x, w1, w2, w_sc, beta1, mean1, var1, beta2, mean2, var2
    const float* x     = (const float*)d_in[0];
    const float* w2    = (const float*)d_in[2];
    const float* w_sc  = (const float*)d_in[3];
    const float* beta2 = (const float*)d_in[7];
    const float* mean2 = (const float*)d_in[8];
    const float* var2  = (const float*)d_in[9];
    float* out = (float*)d_out;

    precompute_kernel<<<F_DIM, 32>>>(w2, w_sc, beta2, mean2, var2);
    resblock_main_kernel<<<GRID_BLOCKS, BLOCK_THREADS>>>(x, out);
}

// round 10
// speedup vs baseline: 1.0030x; 1.0030x over previous
#include <cuda_runtime.h>
#include <cstdint>

// ResBlock_71021579207010 — fused binarized ResBlock (B=32, T=8192, C=F=128, K=2, dil=16).
//
// Algebra (verified R4/R5/R8, rel_err ~2e-7):
//   shortcut[b,t,f] = sum_c sign(x[b,t,c]) * sign(w_sc[0,c,f])           (exact binary dot)
//   conv2 input = ste_sign(relu(...)) == +1  =>  conv2 out constant per (t<16 | t>=16)
//   conv1/bn1/w1/beta1/mean1/var1 are dead.
//   out = relu( shortcut + relu(bn2(const)) )
//
// vs R8 (45.9us main, DRAM 58%, nothing saturated):
//   grid=2048 at 4 blocks/SM resident (592 concurrent) => 3.46 waves; the 272-block
//   tail wave ran the chip half-empty (~13% of wall). Now: PERSISTENT grid of exactly
//   592 blocks (4/SM, one wave, every SM equally loaded); each warp strides rows by
//   4736 (55-56 rows/warp, 1.8% imbalance). Depth-4 register prefetch ring kept via
//   ITERS=56 (mult of 4) + predication. launch_bounds(256,4) pins regs<=64 so
//   residency cannot drop to 3 blocks/SM.

#define T_LEN   8192
#define C_DIM   128
#define F_DIM   128
#define B_DIM   32
#define ROWS_TOTAL (B_DIM * T_LEN)      // 262144

#define NUM_SMS        148
#define BLOCK_THREADS  256
#define WARPS_PER_BLOCK (BLOCK_THREADS / 32)            // 8
#define GRID_BLOCKS    (NUM_SMS * 4)                    // 592 = exactly one full wave
#define TOTAL_WARPS    (GRID_BLOCKS * WARPS_PER_BLOCK)  // 4736
#define ITERS          ((ROWS_TOTAL + TOTAL_WARPS - 1) / TOTAL_WARPS)  // 56 (mult of 4)
#define PF 4                                            // prefetch depth

__device__ uint4 g_wsc[F_DIM];    // packed sign(w_sc): word k bit l <-> channel c = 4*l + k
__device__ float g_clo[F_DIM];    // 128 + relu(bn2(S1))       for t <  16
__device__ float g_chi[F_DIM];    // 128 + relu(bn2(S0+S1))    for t >= 16

// One warp per output channel f; packing uses the SAME ballot construction the
// main kernel applies to x, so bit conventions match by design.
__global__ void precompute_kernel(const float* __restrict__ w2,    // [2,128,128]
                                  const float* __restrict__ w_sc,  // [1,128,128]
                                  const float* __restrict__ beta2,
                                  const float* __restrict__ mean2,
                                  const float* __restrict__ var2) {
    const int f = blockIdx.x;          // 0..127
    const int l = threadIdx.x;         // lane 0..31

    // word k, bit l  <->  channel c = 4*l + k
    unsigned p0 = __ballot_sync(0xffffffffu, w_sc[(4 * l + 0) * F_DIM + f] < 0.0f);
    unsigned p1 = __ballot_sync(0xffffffffu, w_sc[(4 * l + 1) * F_DIM + f] < 0.0f);
    unsigned p2 = __ballot_sync(0xffffffffu, w_sc[(4 * l + 2) * F_DIM + f] < 0.0f);
    unsigned p3 = __ballot_sync(0xffffffffu, w_sc[(4 * l + 3) * F_DIM + f] < 0.0f);

    // Column sums of sign(w2[k,:,f]): count negatives via ballot popc, 4 chans/lane.
    int n0 = 0, n1 = 0;
    #pragma unroll
    for (int j = 0; j < 4; ++j) {
        int c = 4 * l + j;
        unsigned b0 = __ballot_sync(0xffffffffu, w2[(0 * C_DIM + c) * F_DIM + f] < 0.0f);
        unsigned b1 = __ballot_sync(0xffffffffu, w2[(1 * C_DIM + c) * F_DIM + f] < 0.0f);
        n0 += __popc(b0);
        n1 += __popc(b1);
    }

    if (l == 0) {
        g_wsc[f] = make_uint4(p0, p1, p2, p3);
        float S0 = (float)(C_DIM - 2 * n0);
        float S1 = (float)(C_DIM - 2 * n1);
        float inv = rsqrtf(var2[f] + 1e-3f);
        float lo  = (S1      - mean2[f]) * inv + beta2[f];
        float hi  = (S0 + S1 - mean2[f]) * inv + beta2[f];
        // pre-bias by +C_DIM: out = relu((C_DIM - 2*neq) + relu(bn)) = relu(fma(neq,-2,cst))
        g_clo[f] = fmaxf(lo, 0.0f) + (float)C_DIM;
        g_chi[f] = fmaxf(hi, 0.0f) + (float)C_DIM;
    }
}

__global__ __launch_bounds__(BLOCK_THREADS, 4)
void resblock_main_kernel(const float* __restrict__ x, float* __restrict__ out) {
    const int lane  = threadIdx.x & 31;
    const int warp  = threadIdx.x >> 5;
    const int gwarp = blockIdx.x * WARPS_PER_BLOCK + warp;   // 0..4735

    // Per-thread weights/constants in registers (f = 4*lane+j, loop-invariant).
    const uint4* wp = (const uint4*)g_wsc + 4 * lane;
    const uint4 wb0 = wp[0];
    const uint4 wb1 = wp[1];
    const uint4 wb2 = wp[2];
    const uint4 wb3 = wp[3];
    const float4 chi = ((const float4*)g_chi)[lane];
    const float4 clo = ((const float4*)g_clo)[lane];

    // Row r occupies float4-slots [r*32, r*32+32); this thread's slot is +lane.
    const float4* __restrict__ src = (const float4*)x  + lane;
    float4*       __restrict__ dst = (float4*)     out + lane;

    // Depth-4 prefetch ring. First PF rows are always in range:
    // gwarp + 3*4736 <= 4735 + 14208 < 262144.
    float4 buf[PF];
    #pragma unroll
    for (int j = 0; j < PF; ++j)
        buf[j] = __ldcs(src + (size_t)(gwarp + j * TOTAL_WARPS) * (C_DIM / 4));

    #pragma unroll 4
    for (int i = 0; i < ITERS; ++i) {
        const int r = gwarp + i * TOTAL_WARPS;
        const float4 v = buf[i % PF];

        const int rp = gwarp + (i + PF) * TOTAL_WARPS;
        if (rp < ROWS_TOTAL)
            buf[i % PF] = __ldcs(src + (size_t)rp * (C_DIM / 4));

        if (r < ROWS_TOTAL) {
            const unsigned a0 = __ballot_sync(0xffffffffu, v.x < 0.0f);
            const unsigned a1 = __ballot_sync(0xffffffffu, v.y < 0.0f);
            const unsigned a2 = __ballot_sync(0xffffffffu, v.z < 0.0f);
            const unsigned a3 = __ballot_sync(0xffffffffu, v.w < 0.0f);

            const int n0 = __popc(a0 ^ wb0.x) + __popc(a1 ^ wb0.y) + __popc(a2 ^ wb0.z) + __popc(a3 ^ wb0.w);
            const int n1 = __popc(a0 ^ wb1.x) + __popc(a1 ^ wb1.y) + __popc(a2 ^ wb1.z) + __popc(a3 ^ wb1.w);
            const int n2 = __popc(a0 ^ wb2.x) + __popc(a1 ^ wb2.y) + __popc(a2 ^ wb2.z) + __popc(a3 ^ wb2.w);
            const int n3 = __popc(a0 ^ wb3.x) + __popc(a1 ^ wb3.y) + __popc(a2 ^ wb3.z) + __popc(a3 ^ wb3.w);

            const float4 cst = ((r & (T_LEN - 1)) >= 16) ? chi : clo;

            float4 o;
            o.x = fmaxf(fmaf((float)n0, -2.0f, cst.x), 0.0f);
            o.y = fmaxf(fmaf((float)n1, -2.0f, cst.y), 0.0f);
            o.z = fmaxf(fmaf((float)n2, -2.0f, cst.z), 0.0f);
            o.w = fmaxf(fmaf((float)n3, -2.0f, cst.w), 0.0f);

            __stcs(dst + (size_t)r * (F_DIM / 4), o);
        }
    }
}

extern "C" void kernel_launch(void* const* d_in, const int* in_sizes, int n_in,
                              void* d_out, int out_size) {
    // metadata order: x, w1, w2, w_sc, beta1, mean1, var1, beta2, mean2, var2
    const float* x     = (const float*)d_in[0];
    const float* w2    = (const float*)d_in[2];
    const float* w_sc  = (const float*)d_in[3];
    const float* beta2 = (const float*)d_in[7];
    const float* mean2 = (const float*)d_in[8];
    const float* var2  = (const float*)d_in[9];
    float* out = (float*)d_out;

    precompute_kernel<<<F_DIM, 32>>>(w2, w_sc, beta2, mean2, var2);
    resblock_main_kernel<<<GRID_BLOCKS, BLOCK_THREADS>>>(x, out);
}